// round 14
// baseline (speedup 1.0000x reference)
#include <cuda_runtime.h>

typedef unsigned long long ull;

// Problem constants
constexpr int cB = 128, cT = 256, cA = 16, cL = 256, cS = 32, cD = 512;
constexpr int cBT = cB * cT;

// ---------------------------------------------------------------------------
// Scratch (device globals; no runtime allocation allowed)
// ---------------------------------------------------------------------------
__device__ float g_hidden[(long)cBT * 512];  // Qo during scan; MLP hidden after
__device__ float g_hq[cB * 512];             // per-step posterior hidden
__device__ volatile int g_flags[128];        // grid barrier flag slots

// ---------------------------------------------------------------------------
// Packed dual-fp32 FMA (Blackwell f32x2): d.lo += a.lo*b.lo, d.hi += a.hi*b.hi
// ---------------------------------------------------------------------------
__device__ __forceinline__ void ffma2(ull& d, ull a, ull b) {
    asm("fma.rn.f32x2 %0, %1, %2, %0;" : "+l"(d) : "l"(a), "l"(b));
}
__device__ __forceinline__ float2 funpack(ull v) {
    unsigned int lo, hi;
    asm("mov.b64 {%0, %1}, %2;" : "=r"(lo), "=r"(hi) : "l"(v));
    return make_float2(__uint_as_float(lo), __uint_as_float(hi));
}

// ---------------------------------------------------------------------------
// Grid barrier: per-CTA flag slots, 128 parallel pollers. Replay-safe: each
// CTA reads its own slot at kernel start as base (all slots equal between
// runs), targets are base+sid.
// ---------------------------------------------------------------------------
__device__ __forceinline__ void sync_all(int c, int tid, int target) {
    __syncthreads();
    __threadfence();
    if (tid == 0) g_flags[c] = target;
    if (tid < 128) { while (g_flags[tid] < target) { } }
    __threadfence();
    __syncthreads();
}

// ---------------------------------------------------------------------------
// Persistent scan kernel: whole 256-step recurrence in ONE launch.
// grid = 128 CTAs x 256 threads. Phases: AB (GRU) -> C (q1) -> D (q2+sample).
// ---------------------------------------------------------------------------
__global__ __launch_bounds__(256) void rssm_scan(
    const float* __restrict__ actions, const float* __restrict__ eps,
    const float* __restrict__ h0, const float* __restrict__ z0,
    const float* __restrict__ Wih, const float* __restrict__ Whh,
    const float* __restrict__ bih, const float* __restrict__ bhh,
    const float* __restrict__ qW1, const float* __restrict__ qW2,
    const float* __restrict__ qb2,
    float* __restrict__ h_seq, float* __restrict__ z_seq,
    float* __restrict__ pos_mu, float* __restrict__ pos_ls)
{
    __shared__ float sm[5504];
    __shared__ int s_base;
    const int c = blockIdx.x;
    const int tid = threadIdx.x;

    if (tid == 0) s_base = g_flags[c];
    __syncthreads();
    const int base = s_base;
    int sid = 0;

    for (int t = 0; t < cT; t++) {
        const float* hprev = t ? (h_seq + (long)(t - 1) * cD) : h0;
        const long   ldh   = t ? (long)cT * cD : cD;
        const float* zprev = t ? (z_seq + (long)(t - 1) * cS) : z0;
        const long   ldz   = t ? (long)cT * cS : cS;

        // ============ Phase AB: GRU gates -> h_t ===========================
        // grid: 4 btiles(32b) x 32 dtiles(16d). thread: 2b(pair) x 1d x 3g.
        {
            float* As  = sm;           // [32k][34] (pad), m-contiguous
            float* Wsd = sm + 1088;    // [32k][16d][4g] float2 (g=3 used)
            const int bt = c >> 5, dt = c & 31;
            const int b0 = bt * 32, d0 = dt * 16;
            const int bg = tid & 15, dl = tid >> 4;

            ull aR = 0, aZ = 0, aNH = 0, aNI = 0;

            // ---- gh: K=512 over Whh (16 chunks of 32) ----
            for (int ch = 0; ch < 16; ch++) {
                #pragma unroll
                for (int e = 0; e < 4; e++) {
                    int idx = tid + e * 256;
                    int b = idx >> 5, k = idx & 31;
                    As[k * 34 + b] = hprev[(long)(b0 + b) * ldh + ch * 32 + k];
                }
                #pragma unroll
                for (int e = 0; e < 6; e++) {
                    int idx = tid + e * 256;
                    int g = idx >> 9, rem = idx & 511;
                    int k = rem >> 4, d = rem & 15;
                    float w = Whh[(long)(ch * 32 + k) * 1536 + g * 512 + d0 + d];
                    *(float2*)(Wsd + (((k * 16 + d) << 2) + g) * 2) = make_float2(w, w);
                }
                __syncthreads();
                #pragma unroll 8
                for (int kk = 0; kk < 32; kk++) {
                    ull a = *(const ull*)(As + kk * 34 + 2 * bg);
                    const float* wp = Wsd + ((kk * 16 + dl) << 3);
                    ulonglong2 w01 = *(const ulonglong2*)wp;
                    ull w2 = *(const ull*)(wp + 4);
                    ffma2(aR, a, w01.x); ffma2(aZ, a, w01.y); ffma2(aNH, a, w2);
                }
                __syncthreads();
            }
            // ---- gi chunk 1: z_prev (K=32) over Wih rows 0..31 ----
            {
                #pragma unroll
                for (int e = 0; e < 4; e++) {
                    int idx = tid + e * 256;
                    int b = idx >> 5, k = idx & 31;
                    As[k * 34 + b] = zprev[(long)(b0 + b) * ldz + k];
                }
                #pragma unroll
                for (int e = 0; e < 6; e++) {
                    int idx = tid + e * 256;
                    int g = idx >> 9, rem = idx & 511;
                    int k = rem >> 4, d = rem & 15;
                    float w = Wih[(long)k * 1536 + g * 512 + d0 + d];
                    *(float2*)(Wsd + (((k * 16 + d) << 2) + g) * 2) = make_float2(w, w);
                }
                __syncthreads();
                #pragma unroll 8
                for (int kk = 0; kk < 32; kk++) {
                    ull a = *(const ull*)(As + kk * 34 + 2 * bg);
                    const float* wp = Wsd + ((kk * 16 + dl) << 3);
                    ulonglong2 w01 = *(const ulonglong2*)wp;
                    ull w2 = *(const ull*)(wp + 4);
                    ffma2(aR, a, w01.x); ffma2(aZ, a, w01.y); ffma2(aNI, a, w2);
                }
                __syncthreads();
            }
            // ---- gi chunk 2: action_t (K=16) over Wih rows 32..47 ----
            {
                #pragma unroll
                for (int e = 0; e < 2; e++) {
                    int idx = tid + e * 256;
                    int b = idx >> 4, k = idx & 15;
                    As[k * 34 + b] =
                        actions[((long)(b0 + b) * cT + t) * cA + k];
                }
                #pragma unroll
                for (int e = 0; e < 3; e++) {
                    int idx = tid + e * 256;
                    int g = idx >> 8, rem = idx & 255;
                    int k = rem >> 4, d = rem & 15;
                    float w = Wih[(long)(32 + k) * 1536 + g * 512 + d0 + d];
                    *(float2*)(Wsd + (((k * 16 + d) << 2) + g) * 2) = make_float2(w, w);
                }
                __syncthreads();
                #pragma unroll
                for (int kk = 0; kk < 16; kk++) {
                    ull a = *(const ull*)(As + kk * 34 + 2 * bg);
                    const float* wp = Wsd + ((kk * 16 + dl) << 3);
                    ulonglong2 w01 = *(const ulonglong2*)wp;
                    ull w2 = *(const ull*)(wp + 4);
                    ffma2(aR, a, w01.x); ffma2(aZ, a, w01.y); ffma2(aNI, a, w2);
                }
            }
            // ---- gate math + write h_t ----
            const int dg = d0 + dl;
            const float br  = bih[dg]        + bhh[dg];
            const float bz  = bih[512 + dg]  + bhh[512 + dg];
            const float bni = bih[1024 + dg];
            const float bnh = bhh[1024 + dg];
            float2 vR = funpack(aR), vZ = funpack(aZ);
            float2 vNH = funpack(aNH), vNI = funpack(aNI);
            float fR[2]  = {vR.x, vR.y},  fZ[2]  = {vZ.x, vZ.y};
            float fNH[2] = {vNH.x, vNH.y}, fNI[2] = {vNI.x, vNI.y};
            #pragma unroll
            for (int i = 0; i < 2; i++) {
                const int b = b0 + 2 * bg + i;
                float r = 1.0f / (1.0f + expf(-(fR[i] + br)));
                float u = 1.0f / (1.0f + expf(-(fZ[i] + bz)));
                float n = tanhf(fNI[i] + bni + r * (fNH[i] + bnh));
                float hp = hprev[(long)b * ldh + dg];
                h_seq[((long)b * cT + t) * cD + dg] = (1.0f - u) * n + u * hp;
            }
        }
        sid++; sync_all(c, tid, base + sid);

        // ============ Phase C: hq = relu(h_t @ qW1 + Qo) ===================
        // grid: 4 btiles(32b) x 32 ntiles(16n). thread: 2b(pair) x 1n.
        {
            float* As  = sm;           // [32k][34]
            float* Wsd = sm + 1088;    // [32k][16n] float2 dup
            const int bt = c >> 5, nt = c & 31;
            const int b0 = bt * 32, n0 = nt * 16;
            const int bg = tid & 15, nl = tid >> 4;

            ull aq = 0;
            for (int ch = 0; ch < 16; ch++) {
                #pragma unroll
                for (int e = 0; e < 4; e++) {
                    int idx = tid + e * 256;
                    int b = idx >> 5, k = idx & 31;
                    As[k * 34 + b] =
                        h_seq[((long)(b0 + b) * cT + t) * cD + ch * 32 + k];
                }
                #pragma unroll
                for (int e = 0; e < 2; e++) {
                    int idx = tid + e * 256;
                    int k = idx >> 4, n = idx & 15;
                    float w = qW1[(long)(ch * 32 + k) * 512 + n0 + n];
                    *(float2*)(Wsd + (k * 16 + n) * 2) = make_float2(w, w);
                }
                __syncthreads();
                #pragma unroll 8
                for (int kk = 0; kk < 32; kk++) {
                    ull a = *(const ull*)(As + kk * 34 + 2 * bg);
                    ull w = *(const ull*)(Wsd + (kk * 16 + nl) * 2);
                    ffma2(aq, a, w);
                }
                __syncthreads();
            }
            float2 v = funpack(aq);
            float fv[2] = {v.x, v.y};
            #pragma unroll
            for (int i = 0; i < 2; i++) {
                const int b = b0 + 2 * bg + i;
                float val = fv[i] +
                    g_hidden[((long)b * cT + t) * 512 + n0 + nl];
                g_hq[b * 512 + n0 + nl] = fmaxf(val, 0.0f);
            }
        }
        sid++; sync_all(c, tid, base + sid);

        // ============ Phase D: q2 + clip + sample -> z_t ===================
        if (c < 64) {
            float* Hs0 = sm;          // 512
            float* Hs1 = sm + 512;    // 512
            float* Ps  = sm + 1024;   // 512 partials + 128 post
            const int b0 = c * 2;
            for (int i = tid; i < 512; i += 256) {
                Hs0[i] = g_hq[b0 * 512 + i];
                Hs1[i] = g_hq[(b0 + 1) * 512 + i];
            }
            __syncthreads();
            const int j = tid & 63, part = tid >> 6;
            float a0 = 0.0f, a1 = 0.0f;
            const float* Wp = qW2 + (long)(part * 128) * 64 + j;
            #pragma unroll 16
            for (int k = 0; k < 128; k++) {
                float w = Wp[(long)k * 64];
                a0 += Hs0[part * 128 + k] * w;
                a1 += Hs1[part * 128 + k] * w;
            }
            Ps[part * 128 + j]      = a0;
            Ps[part * 128 + 64 + j] = a1;
            __syncthreads();
            if (tid < 64) {
                float v0 = qb2[tid], v1 = qb2[tid];
                #pragma unroll
                for (int p = 0; p < 4; p++) {
                    v0 += Ps[p * 128 + tid];
                    v1 += Ps[p * 128 + 64 + tid];
                }
                Ps[512 + tid]      = v0;
                Ps[512 + 64 + tid] = v1;
            }
            __syncthreads();
            if (tid < 64) {
                int row = tid >> 5, jj = tid & 31;
                int b = b0 + row;
                float mu = Ps[512 + row * 64 + jj];
                float ls = fminf(fmaxf(Ps[512 + row * 64 + 32 + jj], -10.0f), 2.0f);
                long o = ((long)b * cT + t) * cS + jj;
                pos_mu[o] = mu;
                pos_ls[o] = ls;
                z_seq[o]  = mu + eps[o] * expf(ls);
            }
        }
        sid++; sync_all(c, tid, base + sid);
    }
}

// ---------------------------------------------------------------------------
// FFMA2 fp32 GEMM: 64x64 tile, BK=16, 256 threads, 4m x 4n micro-tile with
// n-pairs. A duplicated in smem (broadcast reads), W natural ulonglong2 pairs.
// A(m,k) = k<K1 ? A1[m*lda1+k] : A2[m*lda2+k-K1]
// epi=0: C[gm*ldc+gn] = v ; epi=2 (N==64): cols<32 -> C (mu),
//        cols>=32 -> C2 = clip(v,-10,2)
// ---------------------------------------------------------------------------
__global__ __launch_bounds__(256) void gemm_ff2(
    const float* __restrict__ A1, int lda1, int K1,
    const float* __restrict__ A2, int lda2,
    const float* __restrict__ W, int ldw,
    const float* __restrict__ bias,
    float* __restrict__ C, int ldc,
    float* __restrict__ C2,
    int K, int relu, int epi)
{
    __shared__ float Asd[16 * 130];   // [k][m dup x2] (pad 2)
    __shared__ float Ws[16 * 68];     // [k][n] (pad 4, rows 16B-aligned)
    const int tid = threadIdx.x;
    const int tn = tid & 15, tm = tid >> 4;
    const int bm = blockIdx.y * 64, bn = blockIdx.x * 64;

    ull acc[4][2] = {};

    for (int k0 = 0; k0 < K; k0 += 16) {
        #pragma unroll
        for (int e = 0; e < 4; e++) {
            int idx = tid + e * 256;
            int m = idx >> 4, k = idx & 15;
            int gk = k0 + k;
            float v = (gk < K1) ? A1[(long)(bm + m) * lda1 + gk]
                                : A2[(long)(bm + m) * lda2 + (gk - K1)];
            *(float2*)(Asd + k * 130 + m * 2) = make_float2(v, v);
        }
        #pragma unroll
        for (int e = 0; e < 4; e++) {
            int idx = tid + e * 256;
            int k = idx >> 6, n = idx & 63;
            Ws[k * 68 + n] = W[(long)(k0 + k) * ldw + bn + n];
        }
        __syncthreads();
        #pragma unroll
        for (int kk = 0; kk < 16; kk++) {
            const float* ap = Asd + kk * 130 + tm * 8;
            ull a0 = *(const ull*)(ap);
            ull a1 = *(const ull*)(ap + 2);
            ull a2 = *(const ull*)(ap + 4);
            ull a3 = *(const ull*)(ap + 6);
            ulonglong2 w = *(const ulonglong2*)(Ws + kk * 68 + tn * 4);
            ffma2(acc[0][0], a0, w.x); ffma2(acc[0][1], a0, w.y);
            ffma2(acc[1][0], a1, w.x); ffma2(acc[1][1], a1, w.y);
            ffma2(acc[2][0], a2, w.x); ffma2(acc[2][1], a2, w.y);
            ffma2(acc[3][0], a3, w.x); ffma2(acc[3][1], a3, w.y);
        }
        __syncthreads();
    }

    #pragma unroll
    for (int m = 0; m < 4; m++) {
        int gm = bm + tm * 4 + m;
        #pragma unroll
        for (int np = 0; np < 2; np++) {
            float2 v2 = funpack(acc[m][np]);
            float vv[2] = {v2.x, v2.y};
            #pragma unroll
            for (int h = 0; h < 2; h++) {
                int gn = bn + tn * 4 + np * 2 + h;
                float v = vv[h];
                if (bias) v += bias[gn];
                if (relu) v = fmaxf(v, 0.0f);
                if (epi == 0) {
                    C[(long)gm * ldc + gn] = v;
                } else {  // stats split (N=64): mu | clipped logstd
                    if (gn < 32) C[(long)gm * 32 + gn] = v;
                    else C2[(long)gm * 32 + (gn - 32)] = fminf(fmaxf(v, -10.0f), 2.0f);
                }
            }
        }
    }
}

// ---------------------------------------------------------------------------
// Matvec for reward/done heads: out[r] = dot(H[r,:512], w) + b. Warp per row.
// ---------------------------------------------------------------------------
__global__ __launch_bounds__(256) void matvec512(
    const float* __restrict__ Hd, const float* __restrict__ w,
    const float* __restrict__ bptr, float* __restrict__ out)
{
    const int warp = threadIdx.x >> 5, lane = threadIdx.x & 31;
    const int r = blockIdx.x * 8 + warp;
    const float* hr = Hd + (long)r * 512;
    float s = 0.0f;
    #pragma unroll
    for (int k0 = lane * 4; k0 < 512; k0 += 128) {
        float4 h4 = *reinterpret_cast<const float4*>(&hr[k0]);
        float4 w4 = *reinterpret_cast<const float4*>(&w[k0]);
        s += h4.x * w4.x + h4.y * w4.y + h4.z * w4.z + h4.w * w4.w;
    }
    #pragma unroll
    for (int o = 16; o > 0; o >>= 1) s += __shfl_down_sync(0xffffffffu, s, o);
    if (lane == 0) out[r] = s + bptr[0];
}

// ---------------------------------------------------------------------------
// Host driver — 10 graph nodes total.
// ---------------------------------------------------------------------------
extern "C" void kernel_launch(void* const* d_in, const int* in_sizes, int n_in,
                              void* d_out, int out_size)
{
    const float* actions = (const float*)d_in[0];
    const float* obs     = (const float*)d_in[1];
    const float* eps     = (const float*)d_in[2];
    const float* h0      = (const float*)d_in[3];
    const float* z0      = (const float*)d_in[4];
    const float* Wih     = (const float*)d_in[5];
    const float* Whh     = (const float*)d_in[6];
    const float* bih     = (const float*)d_in[7];
    const float* bhh     = (const float*)d_in[8];
    const float* pW1     = (const float*)d_in[9];
    const float* pb1     = (const float*)d_in[10];
    const float* pW2     = (const float*)d_in[11];
    const float* pb2     = (const float*)d_in[12];
    const float* qW1     = (const float*)d_in[13];
    const float* qb1     = (const float*)d_in[14];
    const float* qW2     = (const float*)d_in[15];
    const float* qb2     = (const float*)d_in[16];
    const float* oW1     = (const float*)d_in[17];
    const float* ob1     = (const float*)d_in[18];
    const float* oW2     = (const float*)d_in[19];
    const float* ob2     = (const float*)d_in[20];
    const float* rW1     = (const float*)d_in[21];
    const float* rb1     = (const float*)d_in[22];
    const float* rW2     = (const float*)d_in[23];
    const float* rb2     = (const float*)d_in[24];
    const float* dW1     = (const float*)d_in[25];
    const float* db1     = (const float*)d_in[26];
    const float* dW2     = (const float*)d_in[27];
    const float* db2     = (const float*)d_in[28];

    float* out    = (float*)d_out;
    float* h_seq  = out;                       // [B,T,512]
    float* z_seq  = h_seq  + (long)cBT * 512;  // [B,T,32]
    float* obs_p  = z_seq  + (long)cBT * 32;   // [B,T,256]
    float* rew_p  = obs_p  + (long)cBT * 256;  // [B,T]
    float* done_p = rew_p  + cBT;              // [B,T]
    float* pri_mu = done_p + cBT;              // [B,T,32]
    float* pri_ls = pri_mu + (long)cBT * 32;
    float* pos_mu = pri_ls + (long)cBT * 32;
    float* pos_ls = pos_mu + (long)cBT * 32;

    float* hidden;
    cudaGetSymbolAddress((void**)&hidden, g_hidden);

    // 1) Precompute Qo = obs_embeds @ qW1[512:768,:] + qb1  (M=BT,K=256,N=512)
    gemm_ff2<<<dim3(512 / 64, cBT / 64), 256>>>(
        obs, cL, 256, nullptr, 0,
        qW1 + 512 * 512, 512, qb1,
        hidden, 512, nullptr, 256, 0, 0);

    // 2) Whole recurrence: ONE persistent kernel
    rssm_scan<<<128, 256>>>(actions, eps, h0, z0,
                            Wih, Whh, bih, bhh,
                            qW1, qW2, qb2,
                            h_seq, z_seq, pos_mu, pos_ls);

    // 3) Batched heads over all B*T rows
    // prior: hidden = relu(h_seq @ pW1 + pb1); stats = hidden @ pW2 + pb2
    gemm_ff2<<<dim3(8, cBT / 64), 256>>>(
        h_seq, 512, 512, nullptr, 0, pW1, 512, pb1,
        hidden, 512, nullptr, 512, 1, 0);
    gemm_ff2<<<dim3(1, cBT / 64), 256>>>(
        hidden, 512, 512, nullptr, 0, pW2, 64, pb2,
        pri_mu, 0, pri_ls, 512, 0, 2);

    // obs head: st = [h|z]
    gemm_ff2<<<dim3(8, cBT / 64), 256>>>(
        h_seq, 512, 512, z_seq, 32, oW1, 512, ob1,
        hidden, 512, nullptr, 544, 1, 0);
    gemm_ff2<<<dim3(4, cBT / 64), 256>>>(
        hidden, 512, 512, nullptr, 0, oW2, 256, ob2,
        obs_p, 256, nullptr, 512, 0, 0);

    // reward head
    gemm_ff2<<<dim3(8, cBT / 64), 256>>>(
        h_seq, 512, 512, z_seq, 32, rW1, 512, rb1,
        hidden, 512, nullptr, 544, 1, 0);
    matvec512<<<cBT / 8, 256>>>(hidden, rW2, rb2, rew_p);

    // done head
    gemm_ff2<<<dim3(8, cBT / 64), 256>>>(
        h_seq, 512, 512, z_seq, 32, dW1, 512, db1,
        hidden, 512, nullptr, 544, 1, 0);
    matvec512<<<cBT / 8, 256>>>(hidden, dW2, db2, done_p);
}

// round 15
// speedup vs baseline: 1.6766x; 1.6766x over previous
#include <cuda_runtime.h>

// Problem constants
constexpr int cB = 128, cT = 256, cA = 16, cL = 256, cS = 32, cD = 512;
constexpr int cBT = cB * cT;

// ---------------------------------------------------------------------------
// Scratch (device globals; no runtime allocation allowed)
// ---------------------------------------------------------------------------
__device__ float g_hidden[(long)cBT * 512];  // Qo during scan; MLP hidden after
__device__ float g_hq[cB * 512];             // per-step posterior hidden
__device__ volatile int g_bar_count;         // grid barrier (self-resetting)
__device__ volatile int g_bar_gen;

// Software grid barrier. Valid because grid (128) <= SM count -> all CTAs
// co-resident. Generation counter persists across launches (equality test),
// count returns to 0 after every barrier -> deterministic across replays.
__device__ __forceinline__ void grid_sync() {
    __syncthreads();
    if (threadIdx.x == 0) {
        __threadfence();
        int gen = g_bar_gen;
        if (atomicAdd((int*)&g_bar_count, 1) == (int)gridDim.x - 1) {
            g_bar_count = 0;
            __threadfence();
            g_bar_gen = gen + 1;
        } else {
            while (g_bar_gen == gen) { __nanosleep(32); }
        }
        __threadfence();
    }
    __syncthreads();
}

// ---------------------------------------------------------------------------
// Persistent scan kernel: the whole 256-step recurrence in ONE launch.
// grid = 128 CTAs x 256 threads. 3 phases + 3 grid syncs per step.
// (R13 version — measured-good.)
// ---------------------------------------------------------------------------
__global__ __launch_bounds__(256) void rssm_scan(
    const float* __restrict__ actions, const float* __restrict__ eps,
    const float* __restrict__ h0, const float* __restrict__ z0,
    const float* __restrict__ Wih, const float* __restrict__ Whh,
    const float* __restrict__ bih, const float* __restrict__ bhh,
    const float* __restrict__ qW1, const float* __restrict__ qW2,
    const float* __restrict__ qb2,
    float* __restrict__ h_seq, float* __restrict__ z_seq,
    float* __restrict__ pos_mu, float* __restrict__ pos_ls)
{
    __shared__ float sm[1664];
    const int c = blockIdx.x;
    const int tid = threadIdx.x;

    for (int t = 0; t < cT; t++) {
        const float* hprev = t ? (h_seq + (long)(t - 1) * cD) : h0;
        const long   ldh   = t ? (long)cT * cD : cD;
        const float* zprev = t ? (z_seq + (long)(t - 1) * cS) : z0;
        const long   ldz   = t ? (long)cT * cS : cS;

        // ================= Phase AB: GRU gates (gh + gi fused) -> h_t ======
        {
            float* As = sm;          // [32][17]  (padded)
            float* Ws = sm + 544;    // [3][16][16]
            const int d  = tid & 15, bg = tid >> 4;   // 16 d x 16 b-groups
            const int dt = c & 31,   bt = c >> 5;     // 32 d-tiles x 4 b-tiles
            const int b0 = bt * 32,  d0 = dt * 16;
            const int lb = tid >> 4, lk = tid & 15;   // load coords
            const int wk = tid >> 4, wd = tid & 15;

            float aR[2] = {0, 0}, aZ[2] = {0, 0};
            float aNH[2] = {0, 0}, aNI[2] = {0, 0};   // n gate: hidden/input SPLIT

            // gh part: K=512 over Whh
            for (int ch = 0; ch < 32; ch++) {
                As[lb * 17 + lk]        = hprev[(long)(b0 + lb) * ldh + ch * 16 + lk];
                As[(lb + 16) * 17 + lk] = hprev[(long)(b0 + lb + 16) * ldh + ch * 16 + lk];
                const float* Wp = Whh + (long)(ch * 16 + wk) * 1536 + d0 + wd;
                Ws[wk * 16 + wd]       = Wp[0];
                Ws[256 + wk * 16 + wd] = Wp[512];
                Ws[512 + wk * 16 + wd] = Wp[1024];
                __syncthreads();
                #pragma unroll
                for (int kk = 0; kk < 16; kk++) {
                    float w0 = Ws[kk * 16 + d];
                    float w1 = Ws[256 + kk * 16 + d];
                    float w2 = Ws[512 + kk * 16 + d];
                    float a0 = As[(bg * 2) * 17 + kk];
                    float a1 = As[(bg * 2 + 1) * 17 + kk];
                    aR[0] += a0 * w0; aZ[0] += a0 * w1; aNH[0] += a0 * w2;
                    aR[1] += a1 * w0; aZ[1] += a1 * w1; aNH[1] += a1 * w2;
                }
                __syncthreads();
            }
            // gi part: K=48 over Wih, x = [z_prev (32) | action_t (16)]
            for (int ch = 0; ch < 3; ch++) {
                float v0, v1;
                if (ch < 2) {
                    v0 = zprev[(long)(b0 + lb) * ldz + ch * 16 + lk];
                    v1 = zprev[(long)(b0 + lb + 16) * ldz + ch * 16 + lk];
                } else {
                    v0 = actions[(long)(b0 + lb) * (cT * cA) + (long)t * cA + lk];
                    v1 = actions[(long)(b0 + lb + 16) * (cT * cA) + (long)t * cA + lk];
                }
                As[lb * 17 + lk] = v0;
                As[(lb + 16) * 17 + lk] = v1;
                const float* Wp = Wih + (long)(ch * 16 + wk) * 1536 + d0 + wd;
                Ws[wk * 16 + wd]       = Wp[0];
                Ws[256 + wk * 16 + wd] = Wp[512];
                Ws[512 + wk * 16 + wd] = Wp[1024];
                __syncthreads();
                #pragma unroll
                for (int kk = 0; kk < 16; kk++) {
                    float w0 = Ws[kk * 16 + d];
                    float w1 = Ws[256 + kk * 16 + d];
                    float w2 = Ws[512 + kk * 16 + d];
                    float a0 = As[(bg * 2) * 17 + kk];
                    float a1 = As[(bg * 2 + 1) * 17 + kk];
                    aR[0] += a0 * w0; aZ[0] += a0 * w1; aNI[0] += a0 * w2;
                    aR[1] += a1 * w0; aZ[1] += a1 * w1; aNI[1] += a1 * w2;
                }
                __syncthreads();
            }
            const int dg = d0 + d;
            const float br  = bih[dg]        + bhh[dg];
            const float bz  = bih[512 + dg]  + bhh[512 + dg];
            const float bni = bih[1024 + dg];
            const float bnh = bhh[1024 + dg];
            #pragma unroll
            for (int i = 0; i < 2; i++) {
                const int b = b0 + bg * 2 + i;
                float r = 1.0f / (1.0f + expf(-(aR[i] + br)));
                float u = 1.0f / (1.0f + expf(-(aZ[i] + bz)));
                float n = tanhf(aNI[i] + bni + r * (aNH[i] + bnh));
                float hp = hprev[(long)b * ldh + dg];
                h_seq[(long)b * (cT * cD) + (long)t * cD + dg] = (1.0f - u) * n + u * hp;
            }
        }
        grid_sync();

        // ================= Phase C: hq = relu(h_t @ qW1 + Qo) ==============
        {
            float* Ah = sm;          // [16][17]
            float* Wq = sm + 272;    // [16][32]
            const int n_l = tid & 31, bg = tid >> 5;   // 32 n x 8 b-groups
            const int nt = c & 15, bt = c >> 4;        // 16 n-tiles x 8 b-tiles
            const int b0 = bt * 16, n0 = nt * 32;
            const int lb = tid >> 4, lk = tid & 15;
            float acc0 = 0.0f, acc1 = 0.0f;

            for (int ch = 0; ch < 32; ch++) {
                Ah[lb * 17 + lk] =
                    h_seq[(long)(b0 + lb) * (cT * cD) + (long)t * cD + ch * 16 + lk];
                {
                    int k = tid >> 5, n = tid & 31;
                    Wq[k * 32 + n]       = qW1[(long)(ch * 16 + k) * 512 + n0 + n];
                    Wq[(k + 8) * 32 + n] = qW1[(long)(ch * 16 + k + 8) * 512 + n0 + n];
                }
                __syncthreads();
                #pragma unroll
                for (int kk = 0; kk < 16; kk++) {
                    float w = Wq[kk * 32 + n_l];
                    acc0 += Ah[(bg * 2) * 17 + kk] * w;
                    acc1 += Ah[(bg * 2 + 1) * 17 + kk] * w;
                }
                __syncthreads();
            }
            const float* Qo = g_hidden;
            const int bA = b0 + bg * 2;
            float q0 = Qo[(long)bA * (cT * 512) + (long)t * 512 + n0 + n_l];
            float q1 = Qo[(long)(bA + 1) * (cT * 512) + (long)t * 512 + n0 + n_l];
            g_hq[bA * 512 + n0 + n_l]       = fmaxf(acc0 + q0, 0.0f);
            g_hq[(bA + 1) * 512 + n0 + n_l] = fmaxf(acc1 + q1, 0.0f);
        }
        grid_sync();

        // ================= Phase D: q2 + clip + sample -> z_t ==============
        if (c < 64) {
            float* Hs0 = sm;          // 512
            float* Hs1 = sm + 512;    // 512
            float* Ps  = sm + 1024;   // 512 partials + 128 post
            const int b0 = c * 2;
            for (int i = tid; i < 512; i += 256) {
                Hs0[i] = g_hq[b0 * 512 + i];
                Hs1[i] = g_hq[(b0 + 1) * 512 + i];
            }
            __syncthreads();
            const int j = tid & 63, part = tid >> 6;
            float a0 = 0.0f, a1 = 0.0f;
            const float* Wp = qW2 + (long)(part * 128) * 64 + j;
            #pragma unroll 16
            for (int k = 0; k < 128; k++) {
                float w = Wp[(long)k * 64];
                a0 += Hs0[part * 128 + k] * w;
                a1 += Hs1[part * 128 + k] * w;
            }
            Ps[part * 128 + j]      = a0;
            Ps[part * 128 + 64 + j] = a1;
            __syncthreads();
            if (tid < 64) {
                float v0 = qb2[tid], v1 = qb2[tid];
                #pragma unroll
                for (int p = 0; p < 4; p++) {
                    v0 += Ps[p * 128 + tid];
                    v1 += Ps[p * 128 + 64 + tid];
                }
                Ps[512 + tid]      = v0;
                Ps[512 + 64 + tid] = v1;
            }
            __syncthreads();
            if (tid < 64) {
                int row = tid >> 5, jj = tid & 31;
                int b = b0 + row;
                float mu = Ps[512 + row * 64 + jj];
                float ls = fminf(fmaxf(Ps[512 + row * 64 + 32 + jj], -10.0f), 2.0f);
                long o = (long)b * (cT * cS) + (long)t * cS + jj;
                pos_mu[o] = mu;
                pos_ls[o] = ls;
                z_seq[o]  = mu + eps[o] * expf(ls);
            }
        }
        grid_sync();
    }
}

// ---------------------------------------------------------------------------
// Big-tile fp32 GEMM: 128x128 tile, BK=16, 256 threads, 8x8 micro-tile.
// 64 FFMA per 4 LDS.128 per kk -> FMA-issue-bound (~50% issue = ~33 TF/s).
// A(m,k) two-source concat by whole BK-chunk: chunks with k0 < K1 read A1,
// the rest read A2 at column (k0-K1). Requires K1 % 16 == 0 (true: K1=512).
// All lda/ldw/ldc multiples of 4; float4 paths throughout.
// ---------------------------------------------------------------------------
__global__ __launch_bounds__(256) void gemm128(
    const float* __restrict__ A1, int lda1, int K1,
    const float* __restrict__ A2, int lda2,
    const float* __restrict__ W, int ldw,
    const float* __restrict__ bias,
    float* __restrict__ C, int ldc,
    int K, int relu)
{
    __shared__ float As[16 * 132];   // [k][m], pad 4
    __shared__ float Ws[16 * 132];   // [k][n], pad 4
    const int tid = threadIdx.x;
    const int tn = tid & 15, tm = tid >> 4;
    const int bm = blockIdx.y * 128, bn = blockIdx.x * 128;

    float acc[8][8] = {};

    for (int k0 = 0; k0 < K; k0 += 16) {
        const float* Ab;
        long lda;
        if (k0 < K1) { Ab = A1 + k0; lda = lda1; }
        else         { Ab = A2 + (k0 - K1); lda = lda2; }

        #pragma unroll
        for (int e = 0; e < 2; e++) {         // A: 128 rows x 4 float4-cols
            int idx = tid + e * 256;
            int row = idx >> 2, c4 = idx & 3;
            float4 v = *reinterpret_cast<const float4*>(Ab + (long)(bm + row) * lda + c4 * 4);
            As[(c4 * 4 + 0) * 132 + row] = v.x;
            As[(c4 * 4 + 1) * 132 + row] = v.y;
            As[(c4 * 4 + 2) * 132 + row] = v.z;
            As[(c4 * 4 + 3) * 132 + row] = v.w;
        }
        #pragma unroll
        for (int e = 0; e < 2; e++) {         // W: 16 k x 32 float4-cols
            int idx = tid + e * 256;
            int k = idx >> 5, n4 = idx & 31;
            *reinterpret_cast<float4*>(Ws + k * 132 + n4 * 4) =
                *reinterpret_cast<const float4*>(W + (long)(k0 + k) * ldw + bn + n4 * 4);
        }
        __syncthreads();

        #pragma unroll
        for (int kk = 0; kk < 16; kk++) {
            float a[8], w[8];
            *reinterpret_cast<float4*>(a)     = *reinterpret_cast<const float4*>(As + kk * 132 + tm * 8);
            *reinterpret_cast<float4*>(a + 4) = *reinterpret_cast<const float4*>(As + kk * 132 + tm * 8 + 4);
            *reinterpret_cast<float4*>(w)     = *reinterpret_cast<const float4*>(Ws + kk * 132 + tn * 8);
            *reinterpret_cast<float4*>(w + 4) = *reinterpret_cast<const float4*>(Ws + kk * 132 + tn * 8 + 4);
            #pragma unroll
            for (int i = 0; i < 8; i++)
                #pragma unroll
                for (int j = 0; j < 8; j++)
                    acc[i][j] += a[i] * w[j];
        }
        __syncthreads();
    }

    #pragma unroll
    for (int i = 0; i < 8; i++) {
        int gm = bm + tm * 8 + i;
        #pragma unroll
        for (int j4 = 0; j4 < 2; j4++) {
            int gn = bn + tn * 8 + j4 * 4;
            float4 o;
            float* ov = reinterpret_cast<float*>(&o);
            #pragma unroll
            for (int l = 0; l < 4; l++) {
                float v = acc[i][j4 * 4 + l];
                if (bias) v += bias[gn + l];
                if (relu) v = fmaxf(v, 0.0f);
                ov[l] = v;
            }
            *reinterpret_cast<float4*>(C + (long)gm * ldc + gn) = o;
        }
    }
}

// ---------------------------------------------------------------------------
// Small-N fp32 GEMM (prior W2, N=64): 64x64 tile, BK=16, 4x4 micro-tile.
// epi=2: cols<32 -> C (mu), cols>=32 -> C2 = clip(v,-10,2). (R13 gemm64.)
// ---------------------------------------------------------------------------
__global__ __launch_bounds__(256) void gemm64(
    const float* __restrict__ A1, int lda1,
    const float* __restrict__ W, int ldw,
    const float* __restrict__ bias,
    float* __restrict__ C, float* __restrict__ C2,
    int K)
{
    __shared__ float As[16][64];
    __shared__ float Ws[16][64];
    const int tid = threadIdx.x;
    const int tn = tid & 15, tm = tid >> 4;
    const int bm = blockIdx.y * 64;

    float acc[4][4] = {};

    for (int k0 = 0; k0 < K; k0 += 16) {
        #pragma unroll
        for (int e = 0; e < 4; e++) {
            int idx = tid + e * 256;
            int m = idx >> 4, k = idx & 15;
            As[k][m] = A1[(long)(bm + m) * lda1 + k0 + k];
        }
        #pragma unroll
        for (int e = 0; e < 4; e++) {
            int idx = tid + e * 256;
            int k = idx >> 6, n = idx & 63;
            Ws[k][n] = W[(long)(k0 + k) * ldw + n];
        }
        __syncthreads();
        #pragma unroll
        for (int kk = 0; kk < 16; kk++) {
            float4 a4 = *reinterpret_cast<const float4*>(&As[kk][tm * 4]);
            float4 w4 = *reinterpret_cast<const float4*>(&Ws[kk][tn * 4]);
            float av[4] = {a4.x, a4.y, a4.z, a4.w};
            float wv[4] = {w4.x, w4.y, w4.z, w4.w};
            #pragma unroll
            for (int i = 0; i < 4; i++)
                #pragma unroll
                for (int j = 0; j < 4; j++)
                    acc[i][j] += av[i] * wv[j];
        }
        __syncthreads();
    }

    #pragma unroll
    for (int i = 0; i < 4; i++) {
        int gm = bm + tm * 4 + i;
        #pragma unroll
        for (int j = 0; j < 4; j++) {
            int gn = tn * 4 + j;
            float v = acc[i][j] + bias[gn];
            if (gn < 32) C[(long)gm * 32 + gn] = v;
            else C2[(long)gm * 32 + (gn - 32)] = fminf(fmaxf(v, -10.0f), 2.0f);
        }
    }
}

// ---------------------------------------------------------------------------
// Matvec for reward/done heads: out[r] = dot(H[r,:512], w) + b. Warp per row.
// ---------------------------------------------------------------------------
__global__ __launch_bounds__(256) void matvec512(
    const float* __restrict__ Hd, const float* __restrict__ w,
    const float* __restrict__ bptr, float* __restrict__ out)
{
    const int warp = threadIdx.x >> 5, lane = threadIdx.x & 31;
    const int r = blockIdx.x * 8 + warp;
    const float* hr = Hd + (long)r * 512;
    float s = 0.0f;
    #pragma unroll
    for (int k0 = lane * 4; k0 < 512; k0 += 128) {
        float4 h4 = *reinterpret_cast<const float4*>(&hr[k0]);
        float4 w4 = *reinterpret_cast<const float4*>(&w[k0]);
        s += h4.x * w4.x + h4.y * w4.y + h4.z * w4.z + h4.w * w4.w;
    }
    #pragma unroll
    for (int o = 16; o > 0; o >>= 1) s += __shfl_down_sync(0xffffffffu, s, o);
    if (lane == 0) out[r] = s + bptr[0];
}

// ---------------------------------------------------------------------------
// Host driver — 10 graph nodes total.
// ---------------------------------------------------------------------------
extern "C" void kernel_launch(void* const* d_in, const int* in_sizes, int n_in,
                              void* d_out, int out_size)
{
    const float* actions = (const float*)d_in[0];
    const float* obs     = (const float*)d_in[1];
    const float* eps     = (const float*)d_in[2];
    const float* h0      = (const float*)d_in[3];
    const float* z0      = (const float*)d_in[4];
    const float* Wih     = (const float*)d_in[5];
    const float* Whh     = (const float*)d_in[6];
    const float* bih     = (const float*)d_in[7];
    const float* bhh     = (const float*)d_in[8];
    const float* pW1     = (const float*)d_in[9];
    const float* pb1     = (const float*)d_in[10];
    const float* pW2     = (const float*)d_in[11];
    const float* pb2     = (const float*)d_in[12];
    const float* qW1     = (const float*)d_in[13];
    const float* qb1     = (const float*)d_in[14];
    const float* qW2     = (const float*)d_in[15];
    const float* qb2     = (const float*)d_in[16];
    const float* oW1     = (const float*)d_in[17];
    const float* ob1     = (const float*)d_in[18];
    const float* oW2     = (const float*)d_in[19];
    const float* ob2     = (const float*)d_in[20];
    const float* rW1     = (const float*)d_in[21];
    const float* rb1     = (const float*)d_in[22];
    const float* rW2     = (const float*)d_in[23];
    const float* rb2     = (const float*)d_in[24];
    const float* dW1     = (const float*)d_in[25];
    const float* db1     = (const float*)d_in[26];
    const float* dW2     = (const float*)d_in[27];
    const float* db2     = (const float*)d_in[28];

    float* out    = (float*)d_out;
    float* h_seq  = out;                       // [B,T,512]
    float* z_seq  = h_seq  + (long)cBT * 512;  // [B,T,32]
    float* obs_p  = z_seq  + (long)cBT * 32;   // [B,T,256]
    float* rew_p  = obs_p  + (long)cBT * 256;  // [B,T]
    float* done_p = rew_p  + cBT;              // [B,T]
    float* pri_mu = done_p + cBT;              // [B,T,32]
    float* pri_ls = pri_mu + (long)cBT * 32;
    float* pos_mu = pri_ls + (long)cBT * 32;
    float* pos_ls = pos_mu + (long)cBT * 32;

    float* hidden;
    cudaGetSymbolAddress((void**)&hidden, g_hidden);

    // 1) Precompute Qo = obs_embeds @ qW1[512:768,:] + qb1  (M=BT,K=256,N=512)
    gemm128<<<dim3(512 / 128, cBT / 128), 256>>>(
        obs, cL, 1 << 30, nullptr, 0,
        qW1 + 512 * 512, 512, qb1,
        hidden, 512, 256, 0);

    // 2) Whole recurrence: ONE persistent kernel
    rssm_scan<<<128, 256>>>(actions, eps, h0, z0,
                            Wih, Whh, bih, bhh,
                            qW1, qW2, qb2,
                            h_seq, z_seq, pos_mu, pos_ls);

    // 3) Batched heads over all B*T rows
    // prior: hidden = relu(h_seq @ pW1 + pb1); stats = hidden @ pW2 + pb2
    gemm128<<<dim3(4, cBT / 128), 256>>>(
        h_seq, 512, 1 << 30, nullptr, 0, pW1, 512, pb1,
        hidden, 512, 512, 1);
    gemm64<<<dim3(1, cBT / 64), 256>>>(
        hidden, 512, pW2, 64, pb2, pri_mu, pri_ls, 512);

    // obs head: st = [h|z]
    gemm128<<<dim3(4, cBT / 128), 256>>>(
        h_seq, 512, 512, z_seq, 32, oW1, 512, ob1,
        hidden, 512, 544, 1);
    gemm128<<<dim3(2, cBT / 128), 256>>>(
        hidden, 512, 1 << 30, nullptr, 0, oW2, 256, ob2,
        obs_p, 256, 512, 0);

    // reward head
    gemm128<<<dim3(4, cBT / 128), 256>>>(
        h_seq, 512, 512, z_seq, 32, rW1, 512, rb1,
        hidden, 512, 544, 1);
    matvec512<<<cBT / 8, 256>>>(hidden, rW2, rb2, rew_p);

    // done head
    gemm128<<<dim3(4, cBT / 128), 256>>>(
        h_seq, 512, 512, z_seq, 32, dW1, 512, db1,
        hidden, 512, 544, 1);
    matvec512<<<cBT / 8, 256>>>(hidden, dW2, db2, done_p);
}

// round 16
// speedup vs baseline: 2.2208x; 1.3246x over previous
#include <cuda_runtime.h>

// Problem constants
constexpr int cB = 128, cT = 256, cA = 16, cL = 256, cS = 32, cD = 512;
constexpr int cBT = cB * cT;

// ---------------------------------------------------------------------------
// Scratch (device globals; no runtime allocation allowed)
// ---------------------------------------------------------------------------
__device__ float g_hidden[(long)cBT * 512];  // Qo during scan; MLP hidden after
__device__ float g_hq[cB * 512];             // per-step posterior hidden
__device__ volatile int g_bar_count;         // grid barrier (self-resetting)
__device__ volatile int g_bar_gen;

// Software grid barrier. Valid because grid (128) <= SM count -> all CTAs
// co-resident. Generation counter persists across launches (equality test),
// count returns to 0 after every barrier -> deterministic across replays.
__device__ __forceinline__ void grid_sync() {
    __syncthreads();
    if (threadIdx.x == 0) {
        __threadfence();
        int gen = g_bar_gen;
        if (atomicAdd((int*)&g_bar_count, 1) == (int)gridDim.x - 1) {
            g_bar_count = 0;
            __threadfence();
            g_bar_gen = gen + 1;
        } else {
            while (g_bar_gen == gen) { __nanosleep(32); }
        }
        __threadfence();
    }
    __syncthreads();
}

// ---------------------------------------------------------------------------
// Persistent scan kernel: whole 256-step recurrence in ONE launch.
// grid = 128 CTAs x 256 threads. Double-buffered smem pipelines per phase:
// one __syncthreads per K-chunk, global latency hidden behind compute.
// ---------------------------------------------------------------------------
__global__ __launch_bounds__(256) void rssm_scan(
    const float* __restrict__ actions, const float* __restrict__ eps,
    const float* __restrict__ h0, const float* __restrict__ z0,
    const float* __restrict__ Wih, const float* __restrict__ Whh,
    const float* __restrict__ bih, const float* __restrict__ bhh,
    const float* __restrict__ qW1, const float* __restrict__ qW2,
    const float* __restrict__ qb2,
    float* __restrict__ h_seq, float* __restrict__ z_seq,
    float* __restrict__ pos_mu, float* __restrict__ pos_ls)
{
    __shared__ float sm[5248];
    const int c = blockIdx.x;
    const int tid = threadIdx.x;

    for (int t = 0; t < cT; t++) {
        const float* hprev = t ? (h_seq + (long)(t - 1) * cD) : h0;
        const long   ldh   = t ? (long)cT * cD : cD;
        const float* zprev = t ? (z_seq + (long)(t - 1) * cS) : z0;
        const long   ldz   = t ? (long)cT * cS : cS;

        // ============ Phase AB: GRU gates (gh + gi fused) -> h_t ===========
        // CTA tile: 32 batch x 16 d x 3 gates. 18 chunks: 16x32k (Whh),
        // 1x32k (z via Wih), 1x16k (action via Wih). Double-buffered.
        {
            float* As0 = sm;           // 2 x [32k][34] (m in 32 + pad2)
            float* Ws0 = sm + 2176;    // 2 x [3g][32k][16d]
            const int bt = c >> 5, dt = c & 31;
            const int b0 = bt * 32, d0 = dt * 16;
            const int dl = tid & 15, bg = tid >> 4;
            const int am = tid >> 3, aq = tid & 7;    // A loads (32k chunks)
            const int am2 = tid >> 2, aq2 = tid & 3;  // A loads (action chunk)

            float aR[2] = {0, 0}, aZ[2] = {0, 0};
            float aNH[2] = {0, 0}, aNI[2] = {0, 0};   // n gate split: hid/inp
            float ra[4], rw[6];

            auto load_c = [&](int i) {
                if (i < 16) {
                    float4 v = *(const float4*)(hprev + (long)(b0 + am) * ldh + i * 32 + 4 * aq);
                    ra[0] = v.x; ra[1] = v.y; ra[2] = v.z; ra[3] = v.w;
                    #pragma unroll
                    for (int e = 0; e < 6; e++) {
                        int idx = tid + e * 256;
                        int g = idx >> 9, rem = idx & 511, k = rem >> 4, d = rem & 15;
                        rw[e] = Whh[(long)(i * 32 + k) * 1536 + g * 512 + d0 + d];
                    }
                } else if (i == 16) {
                    float4 v = *(const float4*)(zprev + (long)(b0 + am) * ldz + 4 * aq);
                    ra[0] = v.x; ra[1] = v.y; ra[2] = v.z; ra[3] = v.w;
                    #pragma unroll
                    for (int e = 0; e < 6; e++) {
                        int idx = tid + e * 256;
                        int g = idx >> 9, rem = idx & 511, k = rem >> 4, d = rem & 15;
                        rw[e] = Wih[(long)k * 1536 + g * 512 + d0 + d];
                    }
                } else {
                    if (tid < 128) {
                        float4 v = *(const float4*)(actions + ((long)(b0 + am2) * cT + t) * cA + 4 * aq2);
                        ra[0] = v.x; ra[1] = v.y; ra[2] = v.z; ra[3] = v.w;
                    }
                    #pragma unroll
                    for (int e = 0; e < 3; e++) {
                        int idx = tid + e * 256;
                        if (idx < 768) {
                            int g = idx >> 8, rem = idx & 255, k = rem >> 4, d = rem & 15;
                            rw[e] = Wih[(long)(32 + k) * 1536 + g * 512 + d0 + d];
                        }
                    }
                }
            };
            auto store_c = [&](int i, int buf) {
                float* A = As0 + buf * 1088;
                float* W = Ws0 + buf * 1536;
                if (i < 17) {
                    #pragma unroll
                    for (int l = 0; l < 4; l++) A[(4 * aq + l) * 34 + am] = ra[l];
                    #pragma unroll
                    for (int e = 0; e < 6; e++) {
                        int idx = tid + e * 256;
                        int g = idx >> 9, rem = idx & 511, k = rem >> 4, d = rem & 15;
                        W[g * 512 + k * 16 + d] = rw[e];
                    }
                } else {
                    if (tid < 128) {
                        #pragma unroll
                        for (int l = 0; l < 4; l++) A[(4 * aq2 + l) * 34 + am2] = ra[l];
                    }
                    #pragma unroll
                    for (int e = 0; e < 3; e++) {
                        int idx = tid + e * 256;
                        if (idx < 768) {
                            int g = idx >> 8, rem = idx & 255, k = rem >> 4, d = rem & 15;
                            W[g * 512 + k * 16 + d] = rw[e];
                        }
                    }
                }
            };
            auto comp = [&](int buf, int kc, float* a3) {
                const float* A = As0 + buf * 1088;
                const float* W = Ws0 + buf * 1536;
                #pragma unroll 8
                for (int kk = 0; kk < kc; kk++) {
                    float2 a = *(const float2*)(A + kk * 34 + 2 * bg);
                    float w0 = W[kk * 16 + dl];
                    float w1 = W[512 + kk * 16 + dl];
                    float w2 = W[1024 + kk * 16 + dl];
                    aR[0] += a.x * w0; aZ[0] += a.x * w1; a3[0] += a.x * w2;
                    aR[1] += a.y * w0; aZ[1] += a.y * w1; a3[1] += a.y * w2;
                }
            };

            load_c(0); store_c(0, 0);
            __syncthreads();
            for (int i = 0; i < 18; i++) {
                if (i < 17) load_c(i + 1);
                comp(i & 1, (i == 17) ? 16 : 32, (i < 16) ? aNH : aNI);
                if (i < 17) store_c(i + 1, (i + 1) & 1);
                __syncthreads();
            }

            const int dg = d0 + dl;
            const float br  = bih[dg]        + bhh[dg];
            const float bz  = bih[512 + dg]  + bhh[512 + dg];
            const float bni = bih[1024 + dg];
            const float bnh = bhh[1024 + dg];
            #pragma unroll
            for (int i = 0; i < 2; i++) {
                const int b = b0 + bg * 2 + i;
                float r = 1.0f / (1.0f + expf(-(aR[i] + br)));
                float u = 1.0f / (1.0f + expf(-(aZ[i] + bz)));
                float n = tanhf(aNI[i] + bni + r * (aNH[i] + bnh));
                float hp = hprev[(long)b * ldh + dg];
                h_seq[((long)b * cT + t) * cD + dg] = (1.0f - u) * n + u * hp;
            }
        }
        grid_sync();

        // ============ Phase C: hq = relu(h_t @ qW1 + Qo) ===================
        // CTA tile: 16 batch x 32 n. 16 chunks of 32k, double-buffered.
        {
            float* As0 = sm;           // 2 x [32k][18] (m in 16 + pad2)
            float* Ws0 = sm + 1152;    // 2 x [32k][32n]
            const int bt = c >> 4, nt = c & 15;
            const int b0 = bt * 16, n0 = nt * 32;
            const int n_l = tid & 31, bg = tid >> 5;
            const int am = tid >> 3, aq = tid & 7;   // tid<128
            const int wk = tid >> 3, wq = tid & 7;

            float acc0 = 0.0f, acc1 = 0.0f;
            float ra[4], rwv[4];

            auto load_c = [&](int i) {
                if (tid < 128) {
                    float4 v = *(const float4*)(h_seq + ((long)(b0 + am) * cT + t) * cD + i * 32 + 4 * aq);
                    ra[0] = v.x; ra[1] = v.y; ra[2] = v.z; ra[3] = v.w;
                }
                float4 w = *(const float4*)(qW1 + (long)(i * 32 + wk) * 512 + n0 + 4 * wq);
                rwv[0] = w.x; rwv[1] = w.y; rwv[2] = w.z; rwv[3] = w.w;
            };
            auto store_c = [&](int buf) {
                float* A = As0 + buf * 576;
                float* W = Ws0 + buf * 1024;
                if (tid < 128) {
                    #pragma unroll
                    for (int l = 0; l < 4; l++) A[(4 * aq + l) * 18 + am] = ra[l];
                }
                *(float4*)(W + wk * 32 + 4 * wq) = make_float4(rwv[0], rwv[1], rwv[2], rwv[3]);
            };

            load_c(0); store_c(0);
            __syncthreads();
            for (int i = 0; i < 16; i++) {
                if (i < 15) load_c(i + 1);
                {
                    const float* A = As0 + (i & 1) * 576;
                    const float* W = Ws0 + (i & 1) * 1024;
                    #pragma unroll 8
                    for (int kk = 0; kk < 32; kk++) {
                        float2 a = *(const float2*)(A + kk * 18 + 2 * bg);
                        float w = W[kk * 32 + n_l];
                        acc0 += a.x * w;
                        acc1 += a.y * w;
                    }
                }
                if (i < 15) store_c((i + 1) & 1);
                __syncthreads();
            }

            const int bA = b0 + bg * 2;
            float q0 = g_hidden[((long)bA * cT + t) * 512 + n0 + n_l];
            float q1 = g_hidden[((long)(bA + 1) * cT + t) * 512 + n0 + n_l];
            g_hq[bA * 512 + n0 + n_l]       = fmaxf(acc0 + q0, 0.0f);
            g_hq[(bA + 1) * 512 + n0 + n_l] = fmaxf(acc1 + q1, 0.0f);
        }
        grid_sync();

        // ============ Phase D: q2 + clip + sample -> z_t ===================
        if (c < 64) {
            float* Hs0 = sm;          // 512
            float* Hs1 = sm + 512;    // 512
            float* Ps  = sm + 1024;   // 512 partials + 128 post
            const int b0 = c * 2;
            for (int i = tid; i < 512; i += 256) {
                Hs0[i] = g_hq[b0 * 512 + i];
                Hs1[i] = g_hq[(b0 + 1) * 512 + i];
            }
            __syncthreads();
            const int j = tid & 63, part = tid >> 6;
            float a0 = 0.0f, a1 = 0.0f;
            const float* Wp = qW2 + (long)(part * 128) * 64 + j;
            #pragma unroll 16
            for (int k = 0; k < 128; k++) {
                float w = Wp[(long)k * 64];
                a0 += Hs0[part * 128 + k] * w;
                a1 += Hs1[part * 128 + k] * w;
            }
            Ps[part * 128 + j]      = a0;
            Ps[part * 128 + 64 + j] = a1;
            __syncthreads();
            if (tid < 64) {
                float v0 = qb2[tid], v1 = qb2[tid];
                #pragma unroll
                for (int p = 0; p < 4; p++) {
                    v0 += Ps[p * 128 + tid];
                    v1 += Ps[p * 128 + 64 + tid];
                }
                Ps[512 + tid]      = v0;
                Ps[512 + 64 + tid] = v1;
            }
            __syncthreads();
            if (tid < 64) {
                int row = tid >> 5, jj = tid & 31;
                int b = b0 + row;
                float mu = Ps[512 + row * 64 + jj];
                float ls = fminf(fmaxf(Ps[512 + row * 64 + 32 + jj], -10.0f), 2.0f);
                long o = ((long)b * cT + t) * cS + jj;
                pos_mu[o] = mu;
                pos_ls[o] = ls;
                z_seq[o]  = mu + eps[o] * expf(ls);
            }
        }
        grid_sync();
    }
}

// ---------------------------------------------------------------------------
// Big-tile fp32 GEMM: 128x128 tile, BK=16, 256 threads, 8x8 micro-tile,
// DOUBLE-BUFFERED (register prefetch + alternate smem buffer, 1 sync/chunk).
// A(m,k) two-source concat by whole BK-chunk (K1 % 16 == 0).
// ---------------------------------------------------------------------------
__global__ __launch_bounds__(256) void gemm128(
    const float* __restrict__ A1, int lda1, int K1,
    const float* __restrict__ A2, int lda2,
    const float* __restrict__ W, int ldw,
    const float* __restrict__ bias,
    float* __restrict__ C, int ldc,
    int K, int relu)
{
    __shared__ float As[2][16 * 132];
    __shared__ float Ws[2][16 * 132];
    const int tid = threadIdx.x;
    const int tn = tid & 15, tm = tid >> 4;
    const int bm = blockIdx.y * 128, bn = blockIdx.x * 128;

    float acc[8][8] = {};
    float raa[8], rww[8];

    auto ld = [&](int k0) {
        const float* Ab; long lda;
        if (k0 < K1) { Ab = A1 + k0; lda = lda1; }
        else         { Ab = A2 + (k0 - K1); lda = lda2; }
        #pragma unroll
        for (int e = 0; e < 2; e++) {
            int idx = tid + e * 256;
            int row = idx >> 2, c4 = idx & 3;
            float4 v = *(const float4*)(Ab + (long)(bm + row) * lda + c4 * 4);
            raa[e * 4 + 0] = v.x; raa[e * 4 + 1] = v.y;
            raa[e * 4 + 2] = v.z; raa[e * 4 + 3] = v.w;
        }
        #pragma unroll
        for (int e = 0; e < 2; e++) {
            int idx = tid + e * 256;
            int k = idx >> 5, n4 = idx & 31;
            float4 v = *(const float4*)(W + (long)(k0 + k) * ldw + bn + n4 * 4);
            rww[e * 4 + 0] = v.x; rww[e * 4 + 1] = v.y;
            rww[e * 4 + 2] = v.z; rww[e * 4 + 3] = v.w;
        }
    };
    auto st = [&](int buf) {
        #pragma unroll
        for (int e = 0; e < 2; e++) {
            int idx = tid + e * 256;
            int row = idx >> 2, c4 = idx & 3;
            #pragma unroll
            for (int l = 0; l < 4; l++)
                As[buf][(c4 * 4 + l) * 132 + row] = raa[e * 4 + l];
        }
        #pragma unroll
        for (int e = 0; e < 2; e++) {
            int idx = tid + e * 256;
            int k = idx >> 5, n4 = idx & 31;
            *(float4*)(&Ws[buf][k * 132 + n4 * 4]) =
                make_float4(rww[e * 4], rww[e * 4 + 1], rww[e * 4 + 2], rww[e * 4 + 3]);
        }
    };

    const int nch = K / 16;
    ld(0); st(0);
    __syncthreads();
    for (int i = 0; i < nch; i++) {
        if (i + 1 < nch) ld((i + 1) * 16);
        {
            const float* Ab = As[i & 1];
            const float* Wb = Ws[i & 1];
            #pragma unroll
            for (int kk = 0; kk < 16; kk++) {
                float a[8], w[8];
                *(float4*)(a)     = *(const float4*)(Ab + kk * 132 + tm * 8);
                *(float4*)(a + 4) = *(const float4*)(Ab + kk * 132 + tm * 8 + 4);
                *(float4*)(w)     = *(const float4*)(Wb + kk * 132 + tn * 8);
                *(float4*)(w + 4) = *(const float4*)(Wb + kk * 132 + tn * 8 + 4);
                #pragma unroll
                for (int x = 0; x < 8; x++)
                    #pragma unroll
                    for (int y = 0; y < 8; y++)
                        acc[x][y] += a[x] * w[y];
            }
        }
        if (i + 1 < nch) st((i + 1) & 1);
        __syncthreads();
    }

    #pragma unroll
    for (int i = 0; i < 8; i++) {
        int gm = bm + tm * 8 + i;
        #pragma unroll
        for (int j4 = 0; j4 < 2; j4++) {
            int gn = bn + tn * 8 + j4 * 4;
            float4 o;
            float* ov = reinterpret_cast<float*>(&o);
            #pragma unroll
            for (int l = 0; l < 4; l++) {
                float v = acc[i][j4 * 4 + l];
                if (bias) v += bias[gn + l];
                if (relu) v = fmaxf(v, 0.0f);
                ov[l] = v;
            }
            *reinterpret_cast<float4*>(C + (long)gm * ldc + gn) = o;
        }
    }
}

// ---------------------------------------------------------------------------
// Small-N fp32 GEMM (prior W2, N=64): 64x64 tile, BK=16, 4x4 micro-tile.
// cols<32 -> C (mu), cols>=32 -> C2 = clip(v,-10,2).
// ---------------------------------------------------------------------------
__global__ __launch_bounds__(256) void gemm64(
    const float* __restrict__ A1, int lda1,
    const float* __restrict__ W, int ldw,
    const float* __restrict__ bias,
    float* __restrict__ C, float* __restrict__ C2,
    int K)
{
    __shared__ float As[16][64];
    __shared__ float Ws[16][64];
    const int tid = threadIdx.x;
    const int tn = tid & 15, tm = tid >> 4;
    const int bm = blockIdx.y * 64;

    float acc[4][4] = {};

    for (int k0 = 0; k0 < K; k0 += 16) {
        #pragma unroll
        for (int e = 0; e < 4; e++) {
            int idx = tid + e * 256;
            int m = idx >> 4, k = idx & 15;
            As[k][m] = A1[(long)(bm + m) * lda1 + k0 + k];
        }
        #pragma unroll
        for (int e = 0; e < 4; e++) {
            int idx = tid + e * 256;
            int k = idx >> 6, n = idx & 63;
            Ws[k][n] = W[(long)(k0 + k) * ldw + n];
        }
        __syncthreads();
        #pragma unroll
        for (int kk = 0; kk < 16; kk++) {
            float4 a4 = *reinterpret_cast<const float4*>(&As[kk][tm * 4]);
            float4 w4 = *reinterpret_cast<const float4*>(&Ws[kk][tn * 4]);
            float av[4] = {a4.x, a4.y, a4.z, a4.w};
            float wv[4] = {w4.x, w4.y, w4.z, w4.w};
            #pragma unroll
            for (int i = 0; i < 4; i++)
                #pragma unroll
                for (int j = 0; j < 4; j++)
                    acc[i][j] += av[i] * wv[j];
        }
        __syncthreads();
    }

    #pragma unroll
    for (int i = 0; i < 4; i++) {
        int gm = bm + tm * 4 + i;
        #pragma unroll
        for (int j = 0; j < 4; j++) {
            int gn = tn * 4 + j;
            float v = acc[i][j] + bias[gn];
            if (gn < 32) C[(long)gm * 32 + gn] = v;
            else C2[(long)gm * 32 + (gn - 32)] = fminf(fmaxf(v, -10.0f), 2.0f);
        }
    }
}

// ---------------------------------------------------------------------------
// Matvec for reward/done heads: out[r] = dot(H[r,:512], w) + b. Warp per row.
// ---------------------------------------------------------------------------
__global__ __launch_bounds__(256) void matvec512(
    const float* __restrict__ Hd, const float* __restrict__ w,
    const float* __restrict__ bptr, float* __restrict__ out)
{
    const int warp = threadIdx.x >> 5, lane = threadIdx.x & 31;
    const int r = blockIdx.x * 8 + warp;
    const float* hr = Hd + (long)r * 512;
    float s = 0.0f;
    #pragma unroll
    for (int k0 = lane * 4; k0 < 512; k0 += 128) {
        float4 h4 = *reinterpret_cast<const float4*>(&hr[k0]);
        float4 w4 = *reinterpret_cast<const float4*>(&w[k0]);
        s += h4.x * w4.x + h4.y * w4.y + h4.z * w4.z + h4.w * w4.w;
    }
    #pragma unroll
    for (int o = 16; o > 0; o >>= 1) s += __shfl_down_sync(0xffffffffu, s, o);
    if (lane == 0) out[r] = s + bptr[0];
}

// ---------------------------------------------------------------------------
// Host driver — 10 graph nodes total.
// ---------------------------------------------------------------------------
extern "C" void kernel_launch(void* const* d_in, const int* in_sizes, int n_in,
                              void* d_out, int out_size)
{
    const float* actions = (const float*)d_in[0];
    const float* obs     = (const float*)d_in[1];
    const float* eps     = (const float*)d_in[2];
    const float* h0      = (const float*)d_in[3];
    const float* z0      = (const float*)d_in[4];
    const float* Wih     = (const float*)d_in[5];
    const float* Whh     = (const float*)d_in[6];
    const float* bih     = (const float*)d_in[7];
    const float* bhh     = (const float*)d_in[8];
    const float* pW1     = (const float*)d_in[9];
    const float* pb1     = (const float*)d_in[10];
    const float* pW2     = (const float*)d_in[11];
    const float* pb2     = (const float*)d_in[12];
    const float* qW1     = (const float*)d_in[13];
    const float* qb1     = (const float*)d_in[14];
    const float* qW2     = (const float*)d_in[15];
    const float* qb2     = (const float*)d_in[16];
    const float* oW1     = (const float*)d_in[17];
    const float* ob1     = (const float*)d_in[18];
    const float* oW2     = (const float*)d_in[19];
    const float* ob2     = (const float*)d_in[20];
    const float* rW1     = (const float*)d_in[21];
    const float* rb1     = (const float*)d_in[22];
    const float* rW2     = (const float*)d_in[23];
    const float* rb2     = (const float*)d_in[24];
    const float* dW1     = (const float*)d_in[25];
    const float* db1     = (const float*)d_in[26];
    const float* dW2     = (const float*)d_in[27];
    const float* db2     = (const float*)d_in[28];

    float* out    = (float*)d_out;
    float* h_seq  = out;                       // [B,T,512]
    float* z_seq  = h_seq  + (long)cBT * 512;  // [B,T,32]
    float* obs_p  = z_seq  + (long)cBT * 32;   // [B,T,256]
    float* rew_p  = obs_p  + (long)cBT * 256;  // [B,T]
    float* done_p = rew_p  + cBT;              // [B,T]
    float* pri_mu = done_p + cBT;              // [B,T,32]
    float* pri_ls = pri_mu + (long)cBT * 32;
    float* pos_mu = pri_ls + (long)cBT * 32;
    float* pos_ls = pos_mu + (long)cBT * 32;

    float* hidden;
    cudaGetSymbolAddress((void**)&hidden, g_hidden);

    // 1) Precompute Qo = obs_embeds @ qW1[512:768,:] + qb1  (M=BT,K=256,N=512)
    gemm128<<<dim3(512 / 128, cBT / 128), 256>>>(
        obs, cL, 1 << 30, nullptr, 0,
        qW1 + 512 * 512, 512, qb1,
        hidden, 512, 256, 0);

    // 2) Whole recurrence: ONE persistent kernel
    rssm_scan<<<128, 256>>>(actions, eps, h0, z0,
                            Wih, Whh, bih, bhh,
                            qW1, qW2, qb2,
                            h_seq, z_seq, pos_mu, pos_ls);

    // 3) Batched heads over all B*T rows
    // prior: hidden = relu(h_seq @ pW1 + pb1); stats = hidden @ pW2 + pb2
    gemm128<<<dim3(4, cBT / 128), 256>>>(
        h_seq, 512, 1 << 30, nullptr, 0, pW1, 512, pb1,
        hidden, 512, 512, 1);
    gemm64<<<dim3(1, cBT / 64), 256>>>(
        hidden, 512, pW2, 64, pb2, pri_mu, pri_ls, 512);

    // obs head: st = [h|z]
    gemm128<<<dim3(4, cBT / 128), 256>>>(
        h_seq, 512, 512, z_seq, 32, oW1, 512, ob1,
        hidden, 512, 544, 1);
    gemm128<<<dim3(2, cBT / 128), 256>>>(
        hidden, 512, 1 << 30, nullptr, 0, oW2, 256, ob2,
        obs_p, 256, 512, 0);

    // reward head
    gemm128<<<dim3(4, cBT / 128), 256>>>(
        h_seq, 512, 512, z_seq, 32, rW1, 512, rb1,
        hidden, 512, 544, 1);
    matvec512<<<cBT / 8, 256>>>(hidden, rW2, rb2, rew_p);

    // done head
    gemm128<<<dim3(4, cBT / 128), 256>>>(
        h_seq, 512, 512, z_seq, 32, dW1, 512, db1,
        hidden, 512, 544, 1);
    matvec512<<<cBT / 8, 256>>>(hidden, dW2, db2, done_p);
}